// round 16
// baseline (speedup 1.0000x reference)
#include <cuda_runtime.h>
#include <cuda_fp16.h>
#include <math.h>
#include <stdint.h>

#define BB   16
#define TT   16
#define OO   10
#define LL   160      // T*O
#define DD   768
#define NHH  12
#define DHH  64
#define GH   14
#define GW   14
#define NTOK (BB*LL)  // 2560

// ---------------- scratch (device globals; no runtime alloc allowed) --------
__device__ float g_x  [NTOK*DD];
__device__ float g_qkv[NTOK*3*DD];

__device__ __half g_h_hi  [NTOK*384];
__device__ __half g_hn_hi [NTOK*DD];
__device__ __half g_att_hi[NTOK*DD];
__device__ __half g_ffn_hi[NTOK*4*DD];

__device__ __half g_w2h  [DD*384];
__device__ __half g_qkvh [3*DD*DD];
__device__ __half g_woh  [DD*DD];
__device__ __half g_fc1h [4*DD*DD];
__device__ __half g_fc2h [DD*4*DD];

// ============================ helpers ========================================
__device__ __forceinline__ uint32_t smem_u32(const void* p) {
    uint32_t a;
    asm("{ .reg .u64 t; cvta.to.shared.u64 t, %1; cvt.u32.u64 %0, t; }" : "=r"(a) : "l"(p));
    return a;
}
__device__ __forceinline__ void split_f16(float v, __half& h, __half& l) {
    h = __float2half_rn(v);
    l = __float2half_rn(v - __half2float(h));
}
__device__ __forceinline__ uint32_t h2pack(__half a, __half b) {
    __half2 h; h.x = a; h.y = b;
    return *(uint32_t*)&h;
}
__device__ __forceinline__ void ldsm4(uint32_t* r, uint32_t addr) {
    asm volatile("ldmatrix.sync.aligned.m8n8.x4.shared.b16 {%0,%1,%2,%3}, [%4];"
        : "=r"(r[0]), "=r"(r[1]), "=r"(r[2]), "=r"(r[3]) : "r"(addr));
}
__device__ __forceinline__ void mma16816(float* c, const uint32_t* a, uint32_t b0, uint32_t b1) {
    asm volatile(
        "mma.sync.aligned.m16n8k16.row.col.f32.f16.f16.f32 "
        "{%0,%1,%2,%3}, {%4,%5,%6,%7}, {%8,%9}, {%0,%1,%2,%3};"
        : "+f"(c[0]), "+f"(c[1]), "+f"(c[2]), "+f"(c[3])
        : "r"(a[0]), "r"(a[1]), "r"(a[2]), "r"(a[3]), "r"(b0), "r"(b1));
}
__device__ __forceinline__ void cpa16(uint32_t dst, const void* src) {
    asm volatile("cp.async.cg.shared.global [%0], [%1], 16;" :: "r"(dst), "l"(src) : "memory");
}
#define CP_COMMIT() asm volatile("cp.async.commit_group;" ::: "memory")
#define CP_WAIT0()  asm volatile("cp.async.wait_group 0;" ::: "memory")

// ---------------- fused: w2 transpose (288 blocks) + embed stage 1 ----------
__global__ void fused_pre_k(
    const float* __restrict__ w2,
    const float* __restrict__ box, const float* __restrict__ w1)
{
    int b = blockIdx.x;
    if (b >= 288) {
        int idx = (b - 288) * 256 + threadIdx.y * 32 + threadIdx.x;
        int m = idx / 384, j = idx - m * 384;
        const float* bx = box + m * 4;
        float acc = bx[0] * w1[j] + bx[1] * w1[384 + j] + bx[2] * w1[768 + j] + bx[3] * w1[1152 + j];
        g_h_hi[idx] = __float2half_rn(fmaxf(acc, 0.0f));
        return;
    }
    // w2 transpose: K=384, N=768, nbx=24
    int nb = (b % 24) * 32, kb = (b / 24) * 32;
    __shared__ float t[32][33];
    int x = threadIdx.x, y = threadIdx.y;   // (32, 8)
#pragma unroll
    for (int i = 0; i < 32; i += 8)
        t[y + i][x] = w2[(size_t)(kb + y + i) * 768 + nb + x];
    __syncthreads();
#pragma unroll
    for (int i = 0; i < 32; i += 8)
        g_w2h[(size_t)(nb + y + i) * 384 + kb + x] = __float2half_rn(t[x][y + i]);
}

// ================= HMMA fp16 GEMM (R12-best config) ==========================
// TN=128: 128 thr, 4 warps (2m x 2n). TN=64: 64 thr, 2 warps (1m x 2n).
// KC=64, 2-stage cp.async, rows 64 halves + 16B pad = 144B stride.
// EXTRA=1 (only on the w2 GEMM): blocks with blockIdx.x >= N/TN transpose the
// other four weights concurrently (they're consumed 2+ launches later).
template<int EPI, int TM, int TN, int EXTRA>
__global__ void __launch_bounds__((TN == 128) ? 128 : 64)
hgemm_k(const __half* __restrict__ Ah, const __half* __restrict__ Bh16,
        const float* __restrict__ bias, const float* __restrict__ res,
        float* __restrict__ Cf, __half* __restrict__ Chi,
        int M, int N, int K,
        const float* __restrict__ xq, const float* __restrict__ xo,
        const float* __restrict__ xf1, const float* __restrict__ xf2)
{
    extern __shared__ __align__(16) __half smbuf[];
    constexpr int NTHR = (TN == 128) ? 128 : 64;
    const int tid = threadIdx.x;

    if (EXTRA) {
        int nblk = N / TN;
        if ((int)blockIdx.x >= nblk) {
            int flat = (blockIdx.x - nblk) * gridDim.y + blockIdx.y;
            if (flat >= 6912) return;
            const float* W; __half* Th; int K2, N2, nbx;
            if (flat < 1728)      { W = xq;  Th = g_qkvh; K2 = 768;  N2 = 2304; nbx = 72; }
            else if (flat < 2304) { flat -= 1728; W = xo;  Th = g_woh;  K2 = 768;  N2 = 768;  nbx = 24; }
            else if (flat < 4608) { flat -= 2304; W = xf1; Th = g_fc1h; K2 = 768;  N2 = 3072; nbx = 96; }
            else                  { flat -= 4608; W = xf2; Th = g_fc2h; K2 = 3072; N2 = 768;  nbx = 24; }
            int nb = (flat % nbx) * 32, kb = (flat / nbx) * 32;
            float* t = (float*)smbuf;    // [32][33]
            int x = tid & 31, y = tid >> 5;   // 64 threads: y in 0..1
#pragma unroll
            for (int i = 0; i < 32; i += 2)
                t[(y + i) * 33 + x] = W[(size_t)(kb + y + i) * N2 + nb + x];
            __syncthreads();
#pragma unroll
            for (int i = 0; i < 32; i += 2)
                Th[(size_t)(nb + y + i) * K2 + kb + x] = __float2half_rn(t[x * 33 + y + i]);
            return;
        }
    }

    constexpr int MW = (TN == 128) ? 2 : 1;
    constexpr int MT = TM / (16 * MW);
    constexpr int PN = (TN / 2) / 16;
    constexpr int NT = PN * 2;
    constexpr uint32_t offB  = (uint32_t)TM * 144;
    constexpr uint32_t STG_B = (uint32_t)(TM + TN) * 144;

    const int wid = tid >> 5, lane = tid & 31;
    const int wm = (MW == 2) ? (wid >> 1) : 0;
    const int wn = wid & 1;
    const int m0 = blockIdx.y * TM, n0 = blockIdx.x * TN;
    const uint32_t smb = smem_u32(smbuf);

    const int nch = K >> 6;

    auto load_stage = [&](int st, int kb) {
        uint32_t sb = smb + (uint32_t)st * STG_B;
#pragma unroll
        for (int s = tid; s < TM * 8; s += NTHR) {
            int row = s >> 3, seg = s & 7;
            uint32_t d = sb + (uint32_t)(row * 144 + seg * 16);
            cpa16(d, Ah + (size_t)(m0 + row) * K + kb + seg * 8);
        }
#pragma unroll
        for (int s = tid; s < TN * 8; s += NTHR) {
            int row = s >> 3, seg = s & 7;
            uint32_t d = sb + (uint32_t)(row * 144 + seg * 16);
            cpa16(d + offB, Bh16 + (size_t)(n0 + row) * K + kb + seg * 8);
        }
    };

    const uint32_t a_lo = (uint32_t)(lane & 15) * 144 + (uint32_t)(lane >> 4) * 16;
    const uint32_t a_wb = (uint32_t)(wm * (MT * 16)) * 144;
    const uint32_t b_wb = (uint32_t)(wn * (PN * 16)) * 144;

    float c[MT][NT][4] = {};

    load_stage(0, 0);
    CP_COMMIT();

    for (int ch = 0; ch < nch; ch++) {
        CP_WAIT0();
        __syncthreads();
        if (ch + 1 < nch) {
            load_stage((ch + 1) & 1, (ch + 1) << 6);
            CP_COMMIT();
        }
        uint32_t sb = smb + (uint32_t)(ch & 1) * STG_B;
#pragma unroll
        for (int ks = 0; ks < 4; ks++) {
            uint32_t koff = ks * 32;
            uint32_t ah[MT][4], bh[PN][4];
#pragma unroll
            for (int mt = 0; mt < MT; mt++) {
                uint32_t off = a_wb + (uint32_t)(mt * 16) * 144 + a_lo + koff;
                ldsm4(ah[mt], sb + off);
            }
#pragma unroll
            for (int p = 0; p < PN; p++) {
                uint32_t off = b_wb + (uint32_t)(p * 16) * 144 + a_lo + koff;
                ldsm4(bh[p], sb + offB + off);
            }
#pragma unroll
            for (int mt = 0; mt < MT; mt++) {
#pragma unroll
                for (int p = 0; p < PN; p++) {
#pragma unroll
                    for (int s = 0; s < 2; s++) {
                        int nt = p * 2 + s;
                        mma16816(c[mt][nt], ah[mt], bh[p][s], bh[p][s + 2]);
                    }
                }
            }
        }
        __syncthreads();
    }

    const int rbase = m0 + wm * (MT * 16) + (lane >> 2);
    const int cbase = n0 + wn * (PN * 16) + (lane & 3) * 2;
#pragma unroll
    for (int mt = 0; mt < MT; mt++) {
#pragma unroll
        for (int rr = 0; rr < 2; rr++) {
            int m = rbase + mt * 16 + rr * 8;
#pragma unroll
            for (int nt = 0; nt < NT; nt++) {
                int n = cbase + nt * 8;
                float v0 = c[mt][nt][rr * 2 + 0];
                float v1 = c[mt][nt][rr * 2 + 1];
                if (EPI == 1) {
                    const float* rp = res + (size_t)(m % LL) * N + n;
                    v0 = fmaxf(v0, 0.0f) + rp[0];
                    v1 = fmaxf(v1, 0.0f) + rp[1];
                    *(float2*)(Cf + (size_t)m * N + n) = make_float2(v0, v1);
                } else if (EPI == 2) {
                    const float* rp = res + (size_t)m * N + n;
                    v0 += bias[n] + rp[0];
                    v1 += bias[n + 1] + rp[1];
                    *(float2*)(Cf + (size_t)m * N + n) = make_float2(v0, v1);
                } else if (EPI == 3) {
                    v0 += bias[n];
                    v1 += bias[n + 1];
                    v0 = 0.5f * v0 * (1.0f + erff(v0 * 0.70710678118654752f));
                    v1 = 0.5f * v1 * (1.0f + erff(v1 * 0.70710678118654752f));
                    *(__half2*)(Chi + (size_t)m * N + n) =
                        __halves2half2(__float2half_rn(v0), __float2half_rn(v1));
                } else {
                    *(float2*)(Cf + (size_t)m * N + n) = make_float2(v0, v1);
                }
            }
        }
    }
}

// ================= HMMA attention: block per (b,h,half), 160 threads ========
#define KSTR 72
#define VSTR 168
#define ATT_SMEM ((160*KSTR + 64*VSTR) * 2)   // 44544 bytes

__global__ void __launch_bounds__(160)
attn_k(const float* __restrict__ qkv, __half* __restrict__ Yhi)
{
    extern __shared__ __half smh[];
    __half* sKh = smh;
    __half* sVh = smh + 160 * KSTR;

    const int bh = blockIdx.x;
    const int half = blockIdx.y;
    const int b = bh / NHH, h = bh - b * NHH;
    const int tid = threadIdx.x;
    const int wid = tid >> 5, lane = tid & 31;
    const int g = lane >> 2, t = lane & 3;

    for (int idx = tid; idx < 160 * 64; idx += 160) {
        int row = idx >> 6, col = idx & 63;
        size_t base = (size_t)(b * LL + row) * 2304 + h * 64 + col;
        sKh[row * KSTR + col] = __float2half_rn(qkv[base + 768]);
        sVh[col * VSTR + row] = __float2half_rn(qkv[base + 1536]);
    }
    __syncthreads();

    const uint32_t kh_b = smem_u32(sKh);
    const uint32_t vh_b = smem_u32(sVh);
    const uint32_t lrow = (uint32_t)(lane & 15);
    const uint32_t lseg = (uint32_t)(lane >> 4) * 16;

    const int mt = half * 5 + wid;
    const size_t qrow0 = (size_t)(b * LL + mt * 16 + g) * 2304 + h * 64;
    const size_t qrow1 = qrow0 + 8 * 2304;

    uint32_t qh[4][4], ql[4][4];
#pragma unroll
    for (int kt = 0; kt < 4; kt++) {
        int c0 = kt * 16 + 2 * t;
        float2 x0 = *(const float2*)(qkv + qrow0 + c0);
        float2 x1 = *(const float2*)(qkv + qrow1 + c0);
        float2 x2 = *(const float2*)(qkv + qrow0 + c0 + 8);
        float2 x3 = *(const float2*)(qkv + qrow1 + c0 + 8);
        float f[4][2] = {{x0.x * 0.125f, x0.y * 0.125f}, {x1.x * 0.125f, x1.y * 0.125f},
                         {x2.x * 0.125f, x2.y * 0.125f}, {x3.x * 0.125f, x3.y * 0.125f}};
#pragma unroll
        for (int a = 0; a < 4; a++) {
            __half h0, l0, h1, l1;
            split_f16(f[a][0], h0, l0);
            split_f16(f[a][1], h1, l1);
            qh[kt][a] = h2pack(h0, h1);
            ql[kt][a] = h2pack(l0, l1);
        }
    }

    float c[20][4];
#pragma unroll
    for (int nt = 0; nt < 20; nt++)
#pragma unroll
        for (int e = 0; e < 4; e++) c[nt][e] = 0.f;

    for (int n2 = 0; n2 < 10; n2++) {
        uint32_t roff = (uint32_t)(n2 * 16) * 144 + lrow * 144 + lseg;
#pragma unroll
        for (int kt = 0; kt < 4; kt++) {
            uint32_t kfh[4];
            ldsm4(kfh, kh_b + roff + kt * 32);
#pragma unroll
            for (int s = 0; s < 2; s++) {
                float* cc = c[n2 * 2 + s];
                mma16816(cc, qh[kt], kfh[s], kfh[s + 2]);
                mma16816(cc, ql[kt], kfh[s], kfh[s + 2]);
            }
        }
    }

    float m0 = -1e30f, m1 = -1e30f;
#pragma unroll
    for (int nt = 0; nt < 20; nt++) {
        m0 = fmaxf(m0, fmaxf(c[nt][0], c[nt][1]));
        m1 = fmaxf(m1, fmaxf(c[nt][2], c[nt][3]));
    }
#pragma unroll
    for (int off = 1; off <= 2; off <<= 1) {
        m0 = fmaxf(m0, __shfl_xor_sync(0xffffffffu, m0, off));
        m1 = fmaxf(m1, __shfl_xor_sync(0xffffffffu, m1, off));
    }
    float s0 = 0.f, s1 = 0.f;
#pragma unroll
    for (int nt = 0; nt < 20; nt++) {
        c[nt][0] = __expf(c[nt][0] - m0);
        c[nt][1] = __expf(c[nt][1] - m0);
        c[nt][2] = __expf(c[nt][2] - m1);
        c[nt][3] = __expf(c[nt][3] - m1);
        s0 += c[nt][0] + c[nt][1];
        s1 += c[nt][2] + c[nt][3];
    }
#pragma unroll
    for (int off = 1; off <= 2; off <<= 1) {
        s0 += __shfl_xor_sync(0xffffffffu, s0, off);
        s1 += __shfl_xor_sync(0xffffffffu, s1, off);
    }
    const float inv0 = 1.0f / s0, inv1 = 1.0f / s1;

    float o[8][4];
#pragma unroll
    for (int nt = 0; nt < 8; nt++)
#pragma unroll
        for (int e = 0; e < 4; e++) o[nt][e] = 0.f;

    for (int k2 = 0; k2 < 10; k2++) {
        uint32_t ph[4], pl[4];
        {
            const float* ca = c[2 * k2];
            const float* cb = c[2 * k2 + 1];
            __half ha, la, hb, lb;
            split_f16(ca[0], ha, la); split_f16(ca[1], hb, lb);
            ph[0] = h2pack(ha, hb); pl[0] = h2pack(la, lb);
            split_f16(ca[2], ha, la); split_f16(ca[3], hb, lb);
            ph[1] = h2pack(ha, hb); pl[1] = h2pack(la, lb);
            split_f16(cb[0], ha, la); split_f16(cb[1], hb, lb);
            ph[2] = h2pack(ha, hb); pl[2] = h2pack(la, lb);
            split_f16(cb[2], ha, la); split_f16(cb[3], hb, lb);
            ph[3] = h2pack(ha, hb); pl[3] = h2pack(la, lb);
        }
#pragma unroll
        for (int n2v = 0; n2v < 4; n2v++) {
            uint32_t roff = (uint32_t)(n2v * 16) * 336 + lrow * 336 + lseg + k2 * 32;
            uint32_t vfh[4];
            ldsm4(vfh, vh_b + roff);
#pragma unroll
            for (int s = 0; s < 2; s++) {
                float* oo = o[n2v * 2 + s];
                mma16816(oo, ph, vfh[s], vfh[s + 2]);
                mma16816(oo, pl, vfh[s], vfh[s + 2]);
            }
        }
    }

    const size_t row0 = (size_t)(b * LL + mt * 16 + g) * DD + h * 64;
    const size_t row1 = row0 + (size_t)8 * DD;
#pragma unroll
    for (int nt = 0; nt < 8; nt++) {
        int col = nt * 8 + 2 * t;
        *(__half2*)(Yhi + row0 + col) =
            __halves2half2(__float2half_rn(o[nt][0] * inv0), __float2half_rn(o[nt][1] * inv0));
        *(__half2*)(Yhi + row1 + col) =
            __halves2half2(__float2half_rn(o[nt][2] * inv1), __float2half_rn(o[nt][3] * inv1));
    }
}

// ---------------- layernorm: warp-per-row, 8 rows/block, shfl-only ----------
__global__ void __launch_bounds__(256)
ln_k(const float* __restrict__ X, const float* __restrict__ g,
     const float* __restrict__ b, __half* __restrict__ Yhi)
{
    const int wid = threadIdx.x >> 5, lane = threadIdx.x & 31;
    const int row = blockIdx.x * 8 + wid;
    const float4* x4 = (const float4*)(X + (size_t)row * DD);

    float4 v[6];
    float s = 0.f, sq = 0.f;
#pragma unroll
    for (int i = 0; i < 6; i++) {
        v[i] = x4[i * 32 + lane];
        s  += v[i].x + v[i].y + v[i].z + v[i].w;
        sq += v[i].x * v[i].x + v[i].y * v[i].y + v[i].z * v[i].z + v[i].w * v[i].w;
    }
#pragma unroll
    for (int off = 16; off; off >>= 1) {
        s  += __shfl_xor_sync(0xffffffffu, s, off);
        sq += __shfl_xor_sync(0xffffffffu, sq, off);
    }
    float mean = s * (1.0f / DD);
    float rstd = rsqrtf(sq * (1.0f / DD) - mean * mean + 1e-5f);

    const float4* g4 = (const float4*)g;
    const float4* b4 = (const float4*)b;
#pragma unroll
    for (int i = 0; i < 6; i++) {
        float4 gg = g4[i * 32 + lane];
        float4 bb = b4[i * 32 + lane];
        float y0 = (v[i].x - mean) * rstd * gg.x + bb.x;
        float y1 = (v[i].y - mean) * rstd * gg.y + bb.y;
        float y2 = (v[i].z - mean) * rstd * gg.z + bb.z;
        float y3 = (v[i].w - mean) * rstd * gg.w + bb.w;
        __half2 p0 = __halves2half2(__float2half_rn(y0), __float2half_rn(y1));
        __half2 p1 = __halves2half2(__float2half_rn(y2), __float2half_rn(y3));
        uint2 pk = make_uint2(*(uint32_t*)&p0, *(uint32_t*)&p1);
        *(uint2*)(Yhi + (size_t)row * DD + (i * 32 + lane) * 4) = pk;
    }
}

// ---------------- box-mask scatter + temporal mean (smem-staged) ------------
__global__ void __launch_bounds__(128)
grid_k(const float* __restrict__ box, float* __restrict__ out)
{
    int blk = blockIdx.x;
    int dc = blk % 6;
    int tg = (blk / 6) & 7;
    int b  = blk / 48;
    int tid = threadIdx.x;

    __shared__ float rows[20][128];
    __shared__ uint32_t flags[196];
    __shared__ float4 bxs[20];

    if (tid < 20) {
        int t = tg * 2 + tid / 10, o = tid % 10;
        const float* bx = box + (size_t)((b * TT + t) * OO + o) * 4;
        float4 v = *(const float4*)bx;
        bxs[tid] = make_float4(fminf(v.x, v.z), fminf(v.y, v.w),
                               fmaxf(v.x, v.z), fmaxf(v.y, v.w));
    }
#pragma unroll 4
    for (int e = 0; e < 20; e++) {
        int t = tg * 2 + e / 10, o = e % 10;
        rows[e][tid] = g_x[(size_t)(b * LL + t * OO + o) * DD + dc * 128 + tid];
    }
    __syncthreads();

    for (int cell = tid; cell < 196; cell += 128) {
        int hh = cell / GW, w = cell % GW;
        float cy = (hh + 0.5f) / 14.0f;
        float cx = (w + 0.5f) / 14.0f;
        uint32_t m = 0;
#pragma unroll
        for (int e = 0; e < 20; e++) {
            float4 v = bxs[e];
            if (cy >= v.y && cy <= v.w && cx >= v.x && cx <= v.z) m |= (1u << e);
        }
        flags[cell] = m;
    }
    __syncthreads();

    size_t obase = ((size_t)(b * 8 + tg) * 196) * DD + dc * 128 + tid;
    for (int cell = 0; cell < 196; cell++) {
        uint32_t mask = flags[cell];
        float acc = 0.f;
        while (mask) {
            int e = __ffs(mask) - 1;
            mask &= mask - 1;
            acc += rows[e][tid];
        }
        out[obase + (size_t)cell * DD] = 0.5f * acc;
    }
}

// ---------------- launch ------------------------------------------------------
extern "C" void kernel_launch(void* const* d_in, const int* in_sizes, int n_in,
                              void* d_out, int out_size)
{
    const float* box  = (const float*)d_in[0];
    const float* cat  = (const float*)d_in[1];
    const float* w1   = (const float*)d_in[2];
    const float* w2   = (const float*)d_in[3];
    const float* ln1g = (const float*)d_in[4];
    const float* ln1b = (const float*)d_in[5];
    const float* wqkv = (const float*)d_in[6];
    const float* wo   = (const float*)d_in[7];
    const float* bo   = (const float*)d_in[8];
    const float* ln2g = (const float*)d_in[9];
    const float* ln2b = (const float*)d_in[10];
    const float* wfc1 = (const float*)d_in[11];
    const float* bfc1 = (const float*)d_in[12];
    const float* wfc2 = (const float*)d_in[13];
    const float* bfc2 = (const float*)d_in[14];
    float* out = (float*)d_out;

    float *gx, *gqkv;
    __half *ghh, *ghnh, *gatth, *gffnh;
    __half *w2h, *qkh, *woh, *f1h, *f2h;
    cudaGetSymbolAddress((void**)&gx,    g_x);
    cudaGetSymbolAddress((void**)&gqkv,  g_qkv);
    cudaGetSymbolAddress((void**)&ghh,   g_h_hi);
    cudaGetSymbolAddress((void**)&ghnh,  g_hn_hi);
    cudaGetSymbolAddress((void**)&gatth, g_att_hi);
    cudaGetSymbolAddress((void**)&gffnh, g_ffn_hi);
    cudaGetSymbolAddress((void**)&w2h,   g_w2h);
    cudaGetSymbolAddress((void**)&qkh,   g_qkvh);
    cudaGetSymbolAddress((void**)&woh,   g_woh);
    cudaGetSymbolAddress((void**)&f1h,   g_fc1h);
    cudaGetSymbolAddress((void**)&f2h,   g_fc2h);

    cudaFuncSetAttribute(attn_k, cudaFuncAttributeMaxDynamicSharedMemorySize, ATT_SMEM);

    const int sm_32_64  = (32 + 64)  * 144 * 2;   // 27648
    const int sm_64_128 = (64 + 128) * 144 * 2;   // 55296
    cudaFuncSetAttribute((const void*)hgemm_k<1, 32, 64, 1>,  cudaFuncAttributeMaxDynamicSharedMemorySize, sm_32_64);
    cudaFuncSetAttribute((const void*)hgemm_k<2, 32, 64, 0>,  cudaFuncAttributeMaxDynamicSharedMemorySize, sm_32_64);
    cudaFuncSetAttribute((const void*)hgemm_k<0, 64, 128, 0>, cudaFuncAttributeMaxDynamicSharedMemorySize, sm_64_128);
    cudaFuncSetAttribute((const void*)hgemm_k<3, 64, 128, 0>, cudaFuncAttributeMaxDynamicSharedMemorySize, sm_64_128);

    // 1) w2 transpose + embed (288 + 3840 blocks)
    fused_pre_k<<<288 + 3840, dim3(32, 8)>>>(w2, box, w1);

    // 2) x = relu(h @ w2) + cat; extra 87*80 blocks transpose qkv/wo/fc1/fc2
    hgemm_k<1, 32, 64, 1><<<dim3(DD / 64 + 87, NTOK / 32), 64, sm_32_64>>>(
        ghh, w2h, nullptr, cat, gx, nullptr, NTOK, DD, 384, wqkv, wo, wfc1, wfc2);

    ln_k<<<NTOK / 8, 256>>>(gx, ln1g, ln1b, ghnh);

    // 4) qkv = hn @ wqkv   (720 CTAs)
    hgemm_k<0, 64, 128, 0><<<dim3(3 * DD / 128, NTOK / 64), 128, sm_64_128>>>(
        ghnh, qkh, nullptr, nullptr, gqkv, nullptr, NTOK, 3 * DD, DD,
        nullptr, nullptr, nullptr, nullptr);

    attn_k<<<dim3(BB * NHH, 2), 160, ATT_SMEM>>>(gqkv, gatth);

    // 6) x = x + att @ wo + bo
    hgemm_k<2, 32, 64, 0><<<dim3(DD / 64, NTOK / 32), 64, sm_32_64>>>(
        gatth, woh, bo, gx, gx, nullptr, NTOK, DD, DD,
        nullptr, nullptr, nullptr, nullptr);

    ln_k<<<NTOK / 8, 256>>>(gx, ln2g, ln2b, ghnh);

    // 8) ffn = gelu(hn @ wfc1 + bfc1) -> fp16
    hgemm_k<3, 64, 128, 0><<<dim3(4 * DD / 128, NTOK / 64), 128, sm_64_128>>>(
        ghnh, f1h, bfc1, nullptr, nullptr, gffnh, NTOK, 4 * DD, DD,
        nullptr, nullptr, nullptr, nullptr);

    // 9) x = x + ffn @ wfc2 + bfc2
    hgemm_k<2, 32, 64, 0><<<dim3(DD / 64, NTOK / 32), 64, sm_32_64>>>(
        gffnh, f2h, bfc2, gx, gx, nullptr, NTOK, DD, 4 * DD,
        nullptr, nullptr, nullptr, nullptr);

    grid_k<<<BB * 8 * 6, 128>>>(box, out);
}

// round 17
// speedup vs baseline: 1.0098x; 1.0098x over previous
#include <cuda_runtime.h>
#include <cuda_fp16.h>
#include <math.h>
#include <stdint.h>

#define BB   16
#define TT   16
#define OO   10
#define LL   160      // T*O
#define DD   768
#define NHH  12
#define DHH  64
#define GH   14
#define GW   14
#define NTOK (BB*LL)  // 2560

// ---------------- scratch (device globals; no runtime alloc allowed) --------
__device__ float g_x  [NTOK*DD];
__device__ float g_qkv[NTOK*3*DD];

__device__ __half g_h_hi  [NTOK*384];
__device__ __half g_hn_hi [NTOK*DD];
__device__ __half g_att_hi[NTOK*DD];
__device__ __half g_ffn_hi[NTOK*4*DD];

__device__ __half g_w2h  [DD*384];
__device__ __half g_qkvh [3*DD*DD];
__device__ __half g_woh  [DD*DD];
__device__ __half g_fc1h [4*DD*DD];
__device__ __half g_fc2h [DD*4*DD];

// ============================ helpers ========================================
__device__ __forceinline__ uint32_t smem_u32(const void* p) {
    uint32_t a;
    asm("{ .reg .u64 t; cvta.to.shared.u64 t, %1; cvt.u32.u64 %0, t; }" : "=r"(a) : "l"(p));
    return a;
}
__device__ __forceinline__ void split_f16(float v, __half& h, __half& l) {
    h = __float2half_rn(v);
    l = __float2half_rn(v - __half2float(h));
}
__device__ __forceinline__ uint32_t h2pack(__half a, __half b) {
    __half2 h; h.x = a; h.y = b;
    return *(uint32_t*)&h;
}
__device__ __forceinline__ void ldsm4(uint32_t* r, uint32_t addr) {
    asm volatile("ldmatrix.sync.aligned.m8n8.x4.shared.b16 {%0,%1,%2,%3}, [%4];"
        : "=r"(r[0]), "=r"(r[1]), "=r"(r[2]), "=r"(r[3]) : "r"(addr));
}
__device__ __forceinline__ void mma16816(float* c, const uint32_t* a, uint32_t b0, uint32_t b1) {
    asm volatile(
        "mma.sync.aligned.m16n8k16.row.col.f32.f16.f16.f32 "
        "{%0,%1,%2,%3}, {%4,%5,%6,%7}, {%8,%9}, {%0,%1,%2,%3};"
        : "+f"(c[0]), "+f"(c[1]), "+f"(c[2]), "+f"(c[3])
        : "r"(a[0]), "r"(a[1]), "r"(a[2]), "r"(a[3]), "r"(b0), "r"(b1));
}
__device__ __forceinline__ void cpa16(uint32_t dst, const void* src) {
    asm volatile("cp.async.cg.shared.global [%0], [%1], 16;" :: "r"(dst), "l"(src) : "memory");
}
#define CP_COMMIT() asm volatile("cp.async.commit_group;" ::: "memory")
#define CP_WAIT0()  asm volatile("cp.async.wait_group 0;" ::: "memory")

// ---------------- fused: weight transpose (fp16 RN) + embed stage 1 ---------
__global__ void fused_pre_k(
    const float* __restrict__ w2, const float* __restrict__ wqkv,
    const float* __restrict__ wo, const float* __restrict__ wfc1,
    const float* __restrict__ wfc2,
    const float* __restrict__ box, const float* __restrict__ w1)
{
    int b = blockIdx.x;
    if (b >= 7200) {
        int idx = (b - 7200) * 256 + threadIdx.y * 32 + threadIdx.x;
        int m = idx / 384, j = idx - m * 384;
        const float* bx = box + m * 4;
        float acc = bx[0] * w1[j] + bx[1] * w1[384 + j] + bx[2] * w1[768 + j] + bx[3] * w1[1152 + j];
        g_h_hi[idx] = __float2half_rn(fmaxf(acc, 0.0f));
        return;
    }
    const float* W; __half* Th; int K, N, nbx;
    if (b < 288)       { W = w2;   Th = g_w2h;  K = 384;  N = 768;  nbx = 24; }
    else if (b < 2016) { b -= 288;  W = wqkv; Th = g_qkvh; K = 768;  N = 2304; nbx = 72; }
    else if (b < 2592) { b -= 2016; W = wo;   Th = g_woh;  K = 768;  N = 768;  nbx = 24; }
    else if (b < 4896) { b -= 2592; W = wfc1; Th = g_fc1h; K = 768;  N = 3072; nbx = 96; }
    else               { b -= 4896; W = wfc2; Th = g_fc2h; K = 3072; N = 768;  nbx = 24; }
    int nb = (b % nbx) * 32, kb = (b / nbx) * 32;

    __shared__ float t[32][33];
    int x = threadIdx.x, y = threadIdx.y;
#pragma unroll
    for (int i = 0; i < 32; i += 8)
        t[y + i][x] = W[(size_t)(kb + y + i) * N + nb + x];
    __syncthreads();
#pragma unroll
    for (int i = 0; i < 32; i += 8)
        Th[(size_t)(nb + y + i) * K + kb + x] = __float2half_rn(t[x][y + i]);
}

// ================= HMMA fp16 GEMM (R12-best config) ==========================
template<int EPI, int TM, int TN>
__global__ void __launch_bounds__((TN == 128) ? 128 : 64)
hgemm_k(const __half* __restrict__ Ah, const __half* __restrict__ Bh16,
        const float* __restrict__ bias, const float* __restrict__ res,
        float* __restrict__ Cf, __half* __restrict__ Chi,
        int M, int N, int K)
{
    extern __shared__ __align__(16) __half smbuf[];
    constexpr int NTHR = (TN == 128) ? 128 : 64;
    constexpr int MW = (TN == 128) ? 2 : 1;
    constexpr int MT = TM / (16 * MW);
    constexpr int PN = (TN / 2) / 16;
    constexpr int NT = PN * 2;
    constexpr uint32_t offB  = (uint32_t)TM * 144;
    constexpr uint32_t STG_B = (uint32_t)(TM + TN) * 144;

    const int tid = threadIdx.x;
    const int wid = tid >> 5, lane = tid & 31;
    const int wm = (MW == 2) ? (wid >> 1) : 0;
    const int wn = wid & 1;
    const int m0 = blockIdx.y * TM, n0 = blockIdx.x * TN;
    const uint32_t smb = smem_u32(smbuf);

    const int nch = K >> 6;

    auto load_stage = [&](int st, int kb) {
        uint32_t sb = smb + (uint32_t)st * STG_B;
#pragma unroll
        for (int s = tid; s < TM * 8; s += NTHR) {
            int row = s >> 3, seg = s & 7;
            uint32_t d = sb + (uint32_t)(row * 144 + seg * 16);
            cpa16(d, Ah + (size_t)(m0 + row) * K + kb + seg * 8);
        }
#pragma unroll
        for (int s = tid; s < TN * 8; s += NTHR) {
            int row = s >> 3, seg = s & 7;
            uint32_t d = sb + (uint32_t)(row * 144 + seg * 16);
            cpa16(d + offB, Bh16 + (size_t)(n0 + row) * K + kb + seg * 8);
        }
    };

    const uint32_t a_lo = (uint32_t)(lane & 15) * 144 + (uint32_t)(lane >> 4) * 16;
    const uint32_t a_wb = (uint32_t)(wm * (MT * 16)) * 144;
    const uint32_t b_wb = (uint32_t)(wn * (PN * 16)) * 144;

    float c[MT][NT][4] = {};

    load_stage(0, 0);
    CP_COMMIT();

    for (int ch = 0; ch < nch; ch++) {
        CP_WAIT0();
        __syncthreads();
        if (ch + 1 < nch) {
            load_stage((ch + 1) & 1, (ch + 1) << 6);
            CP_COMMIT();
        }
        uint32_t sb = smb + (uint32_t)(ch & 1) * STG_B;
#pragma unroll
        for (int ks = 0; ks < 4; ks++) {
            uint32_t koff = ks * 32;
            uint32_t ah[MT][4], bh[PN][4];
#pragma unroll
            for (int mt = 0; mt < MT; mt++) {
                uint32_t off = a_wb + (uint32_t)(mt * 16) * 144 + a_lo + koff;
                ldsm4(ah[mt], sb + off);
            }
#pragma unroll
            for (int p = 0; p < PN; p++) {
                uint32_t off = b_wb + (uint32_t)(p * 16) * 144 + a_lo + koff;
                ldsm4(bh[p], sb + offB + off);
            }
#pragma unroll
            for (int mt = 0; mt < MT; mt++) {
#pragma unroll
                for (int p = 0; p < PN; p++) {
#pragma unroll
                    for (int s = 0; s < 2; s++) {
                        int nt = p * 2 + s;
                        mma16816(c[mt][nt], ah[mt], bh[p][s], bh[p][s + 2]);
                    }
                }
            }
        }
        __syncthreads();
    }

    const int rbase = m0 + wm * (MT * 16) + (lane >> 2);
    const int cbase = n0 + wn * (PN * 16) + (lane & 3) * 2;
#pragma unroll
    for (int mt = 0; mt < MT; mt++) {
#pragma unroll
        for (int rr = 0; rr < 2; rr++) {
            int m = rbase + mt * 16 + rr * 8;
#pragma unroll
            for (int nt = 0; nt < NT; nt++) {
                int n = cbase + nt * 8;
                float v0 = c[mt][nt][rr * 2 + 0];
                float v1 = c[mt][nt][rr * 2 + 1];
                if (EPI == 1) {
                    const float* rp = res + (size_t)(m % LL) * N + n;
                    v0 = fmaxf(v0, 0.0f) + rp[0];
                    v1 = fmaxf(v1, 0.0f) + rp[1];
                    *(float2*)(Cf + (size_t)m * N + n) = make_float2(v0, v1);
                } else if (EPI == 2) {
                    const float* rp = res + (size_t)m * N + n;
                    v0 += bias[n] + rp[0];
                    v1 += bias[n + 1] + rp[1];
                    *(float2*)(Cf + (size_t)m * N + n) = make_float2(v0, v1);
                } else if (EPI == 3) {
                    v0 += bias[n];
                    v1 += bias[n + 1];
                    v0 = 0.5f * v0 * (1.0f + erff(v0 * 0.70710678118654752f));
                    v1 = 0.5f * v1 * (1.0f + erff(v1 * 0.70710678118654752f));
                    *(__half2*)(Chi + (size_t)m * N + n) =
                        __halves2half2(__float2half_rn(v0), __float2half_rn(v1));
                } else {
                    *(float2*)(Cf + (size_t)m * N + n) = make_float2(v0, v1);
                }
            }
        }
    }
}

// ================= HMMA attention: block per (b,h,half), 160 threads ========
// Q 2-term (exact); K,V,P single fp16.
#define KSTR 72
#define VSTR 168
#define ATT_SMEM ((160*KSTR + 64*VSTR) * 2)   // 44544 bytes

__global__ void __launch_bounds__(160)
attn_k(const float* __restrict__ qkv, __half* __restrict__ Yhi)
{
    extern __shared__ __half smh[];
    __half* sKh = smh;
    __half* sVh = smh + 160 * KSTR;

    const int bh = blockIdx.x;
    const int half = blockIdx.y;
    const int b = bh / NHH, h = bh - b * NHH;
    const int tid = threadIdx.x;
    const int wid = tid >> 5, lane = tid & 31;
    const int g = lane >> 2, t = lane & 3;

    for (int idx = tid; idx < 160 * 64; idx += 160) {
        int row = idx >> 6, col = idx & 63;
        size_t base = (size_t)(b * LL + row) * 2304 + h * 64 + col;
        sKh[row * KSTR + col] = __float2half_rn(qkv[base + 768]);
        sVh[col * VSTR + row] = __float2half_rn(qkv[base + 1536]);
    }
    __syncthreads();

    const uint32_t kh_b = smem_u32(sKh);
    const uint32_t vh_b = smem_u32(sVh);
    const uint32_t lrow = (uint32_t)(lane & 15);
    const uint32_t lseg = (uint32_t)(lane >> 4) * 16;

    const int mt = half * 5 + wid;
    const size_t qrow0 = (size_t)(b * LL + mt * 16 + g) * 2304 + h * 64;
    const size_t qrow1 = qrow0 + 8 * 2304;

    uint32_t qh[4][4], ql[4][4];
#pragma unroll
    for (int kt = 0; kt < 4; kt++) {
        int c0 = kt * 16 + 2 * t;
        float2 x0 = *(const float2*)(qkv + qrow0 + c0);
        float2 x1 = *(const float2*)(qkv + qrow1 + c0);
        float2 x2 = *(const float2*)(qkv + qrow0 + c0 + 8);
        float2 x3 = *(const float2*)(qkv + qrow1 + c0 + 8);
        float f[4][2] = {{x0.x * 0.125f, x0.y * 0.125f}, {x1.x * 0.125f, x1.y * 0.125f},
                         {x2.x * 0.125f, x2.y * 0.125f}, {x3.x * 0.125f, x3.y * 0.125f}};
#pragma unroll
        for (int a = 0; a < 4; a++) {
            __half h0, l0, h1, l1;
            split_f16(f[a][0], h0, l0);
            split_f16(f[a][1], h1, l1);
            qh[kt][a] = h2pack(h0, h1);
            ql[kt][a] = h2pack(l0, l1);
        }
    }

    float c[20][4];
#pragma unroll
    for (int nt = 0; nt < 20; nt++)
#pragma unroll
        for (int e = 0; e < 4; e++) c[nt][e] = 0.f;

    for (int n2 = 0; n2 < 10; n2++) {
        uint32_t roff = (uint32_t)(n2 * 16) * 144 + lrow * 144 + lseg;
#pragma unroll
        for (int kt = 0; kt < 4; kt++) {
            uint32_t kfh[4];
            ldsm4(kfh, kh_b + roff + kt * 32);
#pragma unroll
            for (int s = 0; s < 2; s++) {
                float* cc = c[n2 * 2 + s];
                mma16816(cc, qh[kt], kfh[s], kfh[s + 2]);
                mma16816(cc, ql[kt], kfh[s], kfh[s + 2]);
            }
        }
    }

    float m0 = -1e30f, m1 = -1e30f;
#pragma unroll
    for (int nt = 0; nt < 20; nt++) {
        m0 = fmaxf(m0, fmaxf(c[nt][0], c[nt][1]));
        m1 = fmaxf(m1, fmaxf(c[nt][2], c[nt][3]));
    }
#pragma unroll
    for (int off = 1; off <= 2; off <<= 1) {
        m0 = fmaxf(m0, __shfl_xor_sync(0xffffffffu, m0, off));
        m1 = fmaxf(m1, __shfl_xor_sync(0xffffffffu, m1, off));
    }
    float s0 = 0.f, s1 = 0.f;
#pragma unroll
    for (int nt = 0; nt < 20; nt++) {
        c[nt][0] = __expf(c[nt][0] - m0);
        c[nt][1] = __expf(c[nt][1] - m0);
        c[nt][2] = __expf(c[nt][2] - m1);
        c[nt][3] = __expf(c[nt][3] - m1);
        s0 += c[nt][0] + c[nt][1];
        s1 += c[nt][2] + c[nt][3];
    }
#pragma unroll
    for (int off = 1; off <= 2; off <<= 1) {
        s0 += __shfl_xor_sync(0xffffffffu, s0, off);
        s1 += __shfl_xor_sync(0xffffffffu, s1, off);
    }
    const float inv0 = 1.0f / s0, inv1 = 1.0f / s1;

    float o[8][4];
#pragma unroll
    for (int nt = 0; nt < 8; nt++)
#pragma unroll
        for (int e = 0; e < 4; e++) o[nt][e] = 0.f;

    for (int k2 = 0; k2 < 10; k2++) {
        uint32_t ph[4];
        {
            const float* ca = c[2 * k2];
            const float* cb = c[2 * k2 + 1];
            ph[0] = h2pack(__float2half_rn(ca[0]), __float2half_rn(ca[1]));
            ph[1] = h2pack(__float2half_rn(ca[2]), __float2half_rn(ca[3]));
            ph[2] = h2pack(__float2half_rn(cb[0]), __float2half_rn(cb[1]));
            ph[3] = h2pack(__float2half_rn(cb[2]), __float2half_rn(cb[3]));
        }
#pragma unroll
        for (int n2v = 0; n2v < 4; n2v++) {
            uint32_t roff = (uint32_t)(n2v * 16) * 336 + lrow * 336 + lseg + k2 * 32;
            uint32_t vfh[4];
            ldsm4(vfh, vh_b + roff);
#pragma unroll
            for (int s = 0; s < 2; s++) {
                float* oo = o[n2v * 2 + s];
                mma16816(oo, ph, vfh[s], vfh[s + 2]);
            }
        }
    }

    const size_t row0 = (size_t)(b * LL + mt * 16 + g) * DD + h * 64;
    const size_t row1 = row0 + (size_t)8 * DD;
#pragma unroll
    for (int nt = 0; nt < 8; nt++) {
        int col = nt * 8 + 2 * t;
        *(__half2*)(Yhi + row0 + col) =
            __halves2half2(__float2half_rn(o[nt][0] * inv0), __float2half_rn(o[nt][1] * inv0));
        *(__half2*)(Yhi + row1 + col) =
            __halves2half2(__float2half_rn(o[nt][2] * inv1), __float2half_rn(o[nt][3] * inv1));
    }
}

// ---------------- layernorm: warp-per-row, 8 rows/block, shfl-only ----------
__global__ void __launch_bounds__(256)
ln_k(const float* __restrict__ X, const float* __restrict__ g,
     const float* __restrict__ b, __half* __restrict__ Yhi)
{
    const int wid = threadIdx.x >> 5, lane = threadIdx.x & 31;
    const int row = blockIdx.x * 8 + wid;
    const float4* x4 = (const float4*)(X + (size_t)row * DD);

    float4 v[6];
    float s = 0.f, sq = 0.f;
#pragma unroll
    for (int i = 0; i < 6; i++) {
        v[i] = x4[i * 32 + lane];
        s  += v[i].x + v[i].y + v[i].z + v[i].w;
        sq += v[i].x * v[i].x + v[i].y * v[i].y + v[i].z * v[i].z + v[i].w * v[i].w;
    }
#pragma unroll
    for (int off = 16; off; off >>= 1) {
        s  += __shfl_xor_sync(0xffffffffu, s, off);
        sq += __shfl_xor_sync(0xffffffffu, sq, off);
    }
    float mean = s * (1.0f / DD);
    float rstd = rsqrtf(sq * (1.0f / DD) - mean * mean + 1e-5f);

    const float4* g4 = (const float4*)g;
    const float4* b4 = (const float4*)b;
#pragma unroll
    for (int i = 0; i < 6; i++) {
        float4 gg = g4[i * 32 + lane];
        float4 bb = b4[i * 32 + lane];
        float y0 = (v[i].x - mean) * rstd * gg.x + bb.x;
        float y1 = (v[i].y - mean) * rstd * gg.y + bb.y;
        float y2 = (v[i].z - mean) * rstd * gg.z + bb.z;
        float y3 = (v[i].w - mean) * rstd * gg.w + bb.w;
        __half2 p0 = __halves2half2(__float2half_rn(y0), __float2half_rn(y1));
        __half2 p1 = __halves2half2(__float2half_rn(y2), __float2half_rn(y3));
        uint2 pk = make_uint2(*(uint32_t*)&p0, *(uint32_t*)&p1);
        *(uint2*)(Yhi + (size_t)row * DD + (i * 32 + lane) * 4) = pk;
    }
}

// ---------------- box-mask scatter + temporal mean (smem-staged) ------------
__global__ void __launch_bounds__(128)
grid_k(const float* __restrict__ box, float* __restrict__ out)
{
    int blk = blockIdx.x;
    int dc = blk % 6;
    int tg = (blk / 6) & 7;
    int b  = blk / 48;
    int tid = threadIdx.x;

    __shared__ float rows[20][128];
    __shared__ uint32_t flags[196];
    __shared__ float4 bxs[20];

    if (tid < 20) {
        int t = tg * 2 + tid / 10, o = tid % 10;
        const float* bx = box + (size_t)((b * TT + t) * OO + o) * 4;
        float4 v = *(const float4*)bx;
        bxs[tid] = make_float4(fminf(v.x, v.z), fminf(v.y, v.w),
                               fmaxf(v.x, v.z), fmaxf(v.y, v.w));
    }
#pragma unroll 4
    for (int e = 0; e < 20; e++) {
        int t = tg * 2 + e / 10, o = e % 10;
        rows[e][tid] = g_x[(size_t)(b * LL + t * OO + o) * DD + dc * 128 + tid];
    }
    __syncthreads();

    for (int cell = tid; cell < 196; cell += 128) {
        int hh = cell / GW, w = cell % GW;
        float cy = (hh + 0.5f) / 14.0f;
        float cx = (w + 0.5f) / 14.0f;
        uint32_t m = 0;
#pragma unroll
        for (int e = 0; e < 20; e++) {
            float4 v = bxs[e];
            if (cy >= v.y && cy <= v.w && cx >= v.x && cx <= v.z) m |= (1u << e);
        }
        flags[cell] = m;
    }
    __syncthreads();

    size_t obase = ((size_t)(b * 8 + tg) * 196) * DD + dc * 128 + tid;
    for (int cell = 0; cell < 196; cell++) {
        uint32_t mask = flags[cell];
        float acc = 0.f;
        while (mask) {
            int e = __ffs(mask) - 1;
            mask &= mask - 1;
            acc += rows[e][tid];
        }
        out[obase + (size_t)cell * DD] = 0.5f * acc;
    }
}

// ---------------- launch ------------------------------------------------------
extern "C" void kernel_launch(void* const* d_in, const int* in_sizes, int n_in,
                              void* d_out, int out_size)
{
    const float* box  = (const float*)d_in[0];
    const float* cat  = (const float*)d_in[1];
    const float* w1   = (const float*)d_in[2];
    const float* w2   = (const float*)d_in[3];
    const float* ln1g = (const float*)d_in[4];
    const float* ln1b = (const float*)d_in[5];
    const float* wqkv = (const float*)d_in[6];
    const float* wo   = (const float*)d_in[7];
    const float* bo   = (const float*)d_in[8];
    const float* ln2g = (const float*)d_in[9];
    const float* ln2b = (const float*)d_in[10];
    const float* wfc1 = (const float*)d_in[11];
    const float* bfc1 = (const float*)d_in[12];
    const float* wfc2 = (const float*)d_in[13];
    const float* bfc2 = (const float*)d_in[14];
    float* out = (float*)d_out;

    float *gx, *gqkv;
    __half *ghh, *ghnh, *gatth, *gffnh;
    __half *w2h, *qkh, *woh, *f1h, *f2h;
    cudaGetSymbolAddress((void**)&gx,    g_x);
    cudaGetSymbolAddress((void**)&gqkv,  g_qkv);
    cudaGetSymbolAddress((void**)&ghh,   g_h_hi);
    cudaGetSymbolAddress((void**)&ghnh,  g_hn_hi);
    cudaGetSymbolAddress((void**)&gatth, g_att_hi);
    cudaGetSymbolAddress((void**)&gffnh, g_ffn_hi);
    cudaGetSymbolAddress((void**)&w2h,   g_w2h);
    cudaGetSymbolAddress((void**)&qkh,   g_qkvh);
    cudaGetSymbolAddress((void**)&woh,   g_woh);
    cudaGetSymbolAddress((void**)&f1h,   g_fc1h);
    cudaGetSymbolAddress((void**)&f2h,   g_fc2h);

    cudaFuncSetAttribute(attn_k, cudaFuncAttributeMaxDynamicSharedMemorySize, ATT_SMEM);

    const int sm_32_64  = (32 + 64)  * 144 * 2;   // 27648
    const int sm_64_128 = (64 + 128) * 144 * 2;   // 55296
    cudaFuncSetAttribute((const void*)hgemm_k<1, 32, 64>,  cudaFuncAttributeMaxDynamicSharedMemorySize, sm_32_64);
    cudaFuncSetAttribute((const void*)hgemm_k<2, 32, 64>,  cudaFuncAttributeMaxDynamicSharedMemorySize, sm_32_64);
    cudaFuncSetAttribute((const void*)hgemm_k<0, 64, 128>, cudaFuncAttributeMaxDynamicSharedMemorySize, sm_64_128);
    cudaFuncSetAttribute((const void*)hgemm_k<3, 64, 128>, cudaFuncAttributeMaxDynamicSharedMemorySize, sm_64_128);

    fused_pre_k<<<11040, dim3(32, 8)>>>(w2, wqkv, wo, wfc1, wfc2, box, w1);

    // 2) x = relu(h @ w2) + cat
    hgemm_k<1, 32, 64><<<dim3(DD / 64, NTOK / 32), 64, sm_32_64>>>(
        ghh, w2h, nullptr, cat, gx, nullptr, NTOK, DD, 384);

    ln_k<<<NTOK / 8, 256>>>(gx, ln1g, ln1b, ghnh);

    // 4) qkv = hn @ wqkv
    hgemm_k<0, 64, 128><<<dim3(3 * DD / 128, NTOK / 64), 128, sm_64_128>>>(
        ghnh, qkh, nullptr, nullptr, gqkv, nullptr, NTOK, 3 * DD, DD);

    attn_k<<<dim3(BB * NHH, 2), 160, ATT_SMEM>>>(gqkv, gatth);

    // 6) x = x + att @ wo + bo
    hgemm_k<2, 32, 64><<<dim3(DD / 64, NTOK / 32), 64, sm_32_64>>>(
        gatth, woh, bo, gx, gx, nullptr, NTOK, DD, DD);

    ln_k<<<NTOK / 8, 256>>>(gx, ln2g, ln2b, ghnh);

    // 8) ffn = gelu(hn @ wfc1 + bfc1) -> fp16
    hgemm_k<3, 64, 128><<<dim3(4 * DD / 128, NTOK / 64), 128, sm_64_128>>>(
        ghnh, f1h, bfc1, nullptr, nullptr, gffnh, NTOK, 4 * DD, DD);

    // 9) x = x + ffn @ wfc2 + bfc2
    hgemm_k<2, 32, 64><<<dim3(DD / 64, NTOK / 32), 64, sm_32_64>>>(
        gffnh, f2h, bfc2, gx, gx, nullptr, NTOK, DD, 4 * DD);

    grid_k<<<BB * 8 * 6, 128>>>(box, out);
}